// round 10
// baseline (speedup 1.0000x reference)
#include <cuda_runtime.h>
#include <math.h>
#include <stdint.h>

#define Bn 32
#define Sn 128
#define Hn 768
#define NHn 12
#define DHn 64
#define FFn 3072
#define Ln 12
#define Tn 10
#define Cn 16
#define Mrows (Bn*Sn)

// ---------------- scratch (static device allocations; no cudaMalloc) ----------------
__device__ float g_x  [Mrows*Hn];
__device__ float g_q  [Mrows*Hn];
__device__ float g_k  [Mrows*Hn];
__device__ float g_v  [Mrows*Hn];
__device__ float g_ctx[Mrows*Hn];
__device__ float g_y  [Mrows*Hn];
__device__ float g_ff [Mrows*FFn];
__device__ float g_xt [Bn*Hn];
__device__ float g_h  [Bn*Hn];
__device__ float g_gi [Bn*3*Hn];
__device__ float g_gh [Bn*3*Hn];

// ---------------- helpers ----------------
__device__ __forceinline__ float2 blockReduce2(float a, float b) {
    __shared__ float ra[8], rb[8];
    int lane = threadIdx.x & 31, w = threadIdx.x >> 5;
#pragma unroll
    for (int o = 16; o > 0; o >>= 1) {
        a += __shfl_xor_sync(0xffffffffu, a, o);
        b += __shfl_xor_sync(0xffffffffu, b, o);
    }
    if (lane == 0) { ra[w] = a; rb[w] = b; }
    __syncthreads();
    if (threadIdx.x == 0) {
        float sa = 0.f, sb = 0.f;
#pragma unroll
        for (int i = 0; i < 8; i++) { sa += ra[i]; sb += rb[i]; }
        ra[0] = sa; rb[0] = sb;
    }
    __syncthreads();
    return make_float2(ra[0], rb[0]);
}

__device__ __forceinline__ uint32_t f2tf(float f) {
    uint32_t r;
    asm("cvt.rna.tf32.f32 %0, %1;" : "=r"(r) : "f"(f));
    return r;
}

__device__ __forceinline__ void mma_tf32(float* c, const uint32_t* a, const uint32_t* b) {
    asm volatile(
        "mma.sync.aligned.m16n8k8.row.col.f32.tf32.tf32.f32 "
        "{%0,%1,%2,%3}, {%4,%5,%6,%7}, {%8,%9}, {%0,%1,%2,%3};"
        : "+f"(c[0]), "+f"(c[1]), "+f"(c[2]), "+f"(c[3])
        : "r"(a[0]), "r"(a[1]), "r"(a[2]), "r"(a[3]), "r"(b[0]), "r"(b[1]));
}

__device__ __forceinline__ void cp16(uint32_t dst, const void* src) {
    asm volatile("cp.async.cg.shared.global [%0], [%1], 16;" :: "r"(dst), "l"(src));
}

// ---------------- TF32 tensor-core GEMM core ----------------
// C[M,N] = A[M,K] @ B[K,N] + bias, optional exact GELU.
// BM=128, BN=64, BK=16, 256 threads (8 warps: 4 along M, 2 along N),
// warp tile 32x32 (m16n8k8), 3-stage cp.async ring, 1 sync/iter.
#define AS_LD 20
#define BS_LD 72
#define NSTG 3

struct TGemmSmem {
    float As[NSTG][128][AS_LD];
    float Bs[NSTG][16][BS_LD];
};

__device__ __forceinline__ void tgemm_core(
    const float* __restrict__ A, const float* __restrict__ B,
    const float* __restrict__ bias, float* __restrict__ C,
    int N, int K, int act, int brow, int bcol, TGemmSmem& sm)
{
    int tid = threadIdx.x;
    int warp = tid >> 5, lane = tid & 31;
    int g = lane >> 2, t = lane & 3;
    int warpM = (warp >> 1) * 32;   // 4 warp rows of 32
    int warpN = (warp & 1) * 32;    // 2 warp cols of 32

    float acc[2][4][4];
#pragma unroll
    for (int mi = 0; mi < 2; mi++)
#pragma unroll
        for (int ni = 0; ni < 4; ni++)
#pragma unroll
            for (int r = 0; r < 4; r++) acc[mi][ni][r] = 0.f;

    uint32_t as_base = (uint32_t)__cvta_generic_to_shared(&sm.As[0][0][0]);
    uint32_t bs_base = (uint32_t)__cvta_generic_to_shared(&sm.Bs[0][0][0]);

    int a_row = tid >> 1;            // 0..127
    int a_c4  = (tid & 1) * 2;       // two float4 slots
    int b_row = tid >> 4;            // 0..15
    int b_c4  = tid & 15;            // 0..15 -> col*4
    int NT = K >> 4;

    auto load_tile = [&](int it, int st) {
        int k0 = it << 4;
#pragma unroll
        for (int i = 0; i < 2; i++) {
            const float* src = A + (size_t)(brow + a_row) * K + k0 + (a_c4 + i) * 4;
            uint32_t dst = as_base + (uint32_t)((st * 128 * AS_LD) + a_row * AS_LD + (a_c4 + i) * 4) * 4u;
            cp16(dst, src);
        }
        {
            const float* src = B + (size_t)(k0 + b_row) * N + bcol + b_c4 * 4;
            uint32_t dst = bs_base + (uint32_t)((st * 16 * BS_LD) + b_row * BS_LD + b_c4 * 4) * 4u;
            cp16(dst, src);
        }
        asm volatile("cp.async.commit_group;");
    };

    load_tile(0, 0);
    if (NT > 1) load_tile(1, 1);

    for (int it = 0; it < NT; ++it) {
        int st = it % NSTG;
        if (it < NT - 1) asm volatile("cp.async.wait_group 1;");
        else             asm volatile("cp.async.wait_group 0;");
        __syncthreads();                 // stage st ready; all warps done with stage (it-1)%NSTG
        if (it + 2 < NT) load_tile(it + 2, (it + 2) % NSTG);  // overwrites stage computed at it-1

#pragma unroll
        for (int ks = 0; ks < 2; ++ks) {
            int kk = ks * 8;
            uint32_t af[2][4], bf[4][2];
#pragma unroll
            for (int mi = 0; mi < 2; mi++) {
                int r0 = warpM + mi * 16 + g;
                af[mi][0] = f2tf(sm.As[st][r0][kk + t]);
                af[mi][1] = f2tf(sm.As[st][r0 + 8][kk + t]);
                af[mi][2] = f2tf(sm.As[st][r0][kk + t + 4]);
                af[mi][3] = f2tf(sm.As[st][r0 + 8][kk + t + 4]);
            }
#pragma unroll
            for (int ni = 0; ni < 4; ni++) {
                int c0 = warpN + ni * 8 + g;
                bf[ni][0] = f2tf(sm.Bs[st][kk + t][c0]);
                bf[ni][1] = f2tf(sm.Bs[st][kk + t + 4][c0]);
            }
#pragma unroll
            for (int mi = 0; mi < 2; mi++)
#pragma unroll
                for (int ni = 0; ni < 4; ni++)
                    mma_tf32(acc[mi][ni], af[mi], bf[ni]);
        }
    }

    // epilogue
#pragma unroll
    for (int mi = 0; mi < 2; mi++) {
        int r0 = brow + warpM + mi * 16 + g;
#pragma unroll
        for (int ni = 0; ni < 4; ni++) {
            int c = bcol + warpN + ni * 8 + t * 2;
            float b0 = bias[c], b1 = bias[c + 1];
            float v0 = acc[mi][ni][0] + b0, v1 = acc[mi][ni][1] + b1;
            float v2 = acc[mi][ni][2] + b0, v3 = acc[mi][ni][3] + b1;
            if (act == 1) {
                v0 = 0.5f * v0 * (1.0f + erff(v0 * 0.70710678118654752f));
                v1 = 0.5f * v1 * (1.0f + erff(v1 * 0.70710678118654752f));
                v2 = 0.5f * v2 * (1.0f + erff(v2 * 0.70710678118654752f));
                v3 = 0.5f * v3 * (1.0f + erff(v3 * 0.70710678118654752f));
            }
            *(float2*)&C[(size_t)r0 * N + c] = make_float2(v0, v1);
            *(float2*)&C[(size_t)(r0 + 8) * N + c] = make_float2(v2, v3);
        }
    }
}

__global__ void __launch_bounds__(256, 3) tgemm_kernel(
    const float* __restrict__ A, const float* __restrict__ B,
    const float* __restrict__ bias, float* __restrict__ C,
    int N, int K, int act)
{
    __shared__ TGemmSmem sm;
    tgemm_core(A, B, bias, C, N, K, act, blockIdx.y * 128, blockIdx.x * 64, sm);
}

// fused Q/K/V: grid.z selects which projection
__global__ void __launch_bounds__(256, 3) qkv_gemm_kernel(
    const float* __restrict__ A,
    const float* __restrict__ Wq, const float* __restrict__ Wk, const float* __restrict__ Wv,
    const float* __restrict__ bq, const float* __restrict__ bk, const float* __restrict__ bv,
    float* __restrict__ q, float* __restrict__ k, float* __restrict__ v)
{
    __shared__ TGemmSmem sm;
    int z = blockIdx.z;
    const float* B = (z == 0) ? Wq : (z == 1) ? Wk : Wv;
    const float* bias = (z == 0) ? bq : (z == 1) ? bk : bv;
    float* C = (z == 0) ? q : (z == 1) ? k : v;
    tgemm_core(A, B, bias, C, Hn, Hn, 0, blockIdx.y * 128, blockIdx.x * 64, sm);
}

// ---------------- embedding + LN ----------------
__global__ void __launch_bounds__(256) embed_ln_kernel(
    const int* __restrict__ ids, const float* __restrict__ ew,
    const float* __restrict__ ep, const float* __restrict__ et,
    const float* __restrict__ g, const float* __restrict__ bb,
    float* __restrict__ x)
{
    int row = blockIdx.x;
    int s = row % Sn;
    int id = ids[row];
    float vals[3]; float sum = 0.f, sq = 0.f;
#pragma unroll
    for (int i = 0; i < 3; i++) {
        int hh = threadIdx.x + i * 256;
        float v = ew[(size_t)id * Hn + hh] + ep[(size_t)s * Hn + hh] + et[hh];
        vals[i] = v; sum += v; sq += v * v;
    }
    float2 r = blockReduce2(sum, sq);
    float m = r.x * (1.f / Hn);
    float var = r.y * (1.f / Hn) - m * m;
    float rs = rsqrtf(var + 1e-12f);
#pragma unroll
    for (int i = 0; i < 3; i++) {
        int hh = threadIdx.x + i * 256;
        x[(size_t)row * Hn + hh] = (vals[i] - m) * rs * g[hh] + bb[hh];
    }
}

// ---------------- residual add + LN:  x = LN(x + t) ----------------
__global__ void __launch_bounds__(256) add_ln_kernel(
    float* __restrict__ x, const float* __restrict__ t,
    const float* __restrict__ g, const float* __restrict__ bb)
{
    size_t base = (size_t)blockIdx.x * Hn;
    float vals[3]; float sum = 0.f, sq = 0.f;
#pragma unroll
    for (int i = 0; i < 3; i++) {
        int hh = threadIdx.x + i * 256;
        float v = x[base + hh] + t[base + hh];
        vals[i] = v; sum += v; sq += v * v;
    }
    float2 r = blockReduce2(sum, sq);
    float m = r.x * (1.f / Hn);
    float var = r.y * (1.f / Hn) - m * m;
    float rs = rsqrtf(var + 1e-12f);
#pragma unroll
    for (int i = 0; i < 3; i++) {
        int hh = threadIdx.x + i * 256;
        x[base + hh] = (vals[i] - m) * rs * g[hh] + bb[hh];
    }
}

// ---------------- fused attention per (head, batch) ----------------
#define ATTN_SMEM ((128*64*2 + 128*129 + 128) * 4)
__global__ void __launch_bounds__(128) attn_kernel(
    const float* __restrict__ q, const float* __restrict__ k,
    const float* __restrict__ v, const int* __restrict__ mask,
    float* __restrict__ ctx)
{
    extern __shared__ float sm[];
    float* ks = sm;
    float* vs = sm + 128 * 64;
    float* sc = sm + 2 * 128 * 64;
    float* ms = sc + 128 * 129;
    int h = blockIdx.x, b = blockIdx.y;
    int tid = threadIdx.x;
    const float scale = 0.125f;
    size_t base = ((size_t)b * Sn) * Hn + h * DHn;

    for (int idx = tid; idx < 128 * 64; idx += 128) {
        int s = idx >> 6, d = idx & 63;
        ks[idx] = k[base + (size_t)s * Hn + d];
        vs[idx] = v[base + (size_t)s * Hn + d];
    }
    ms[tid] = (1.0f - (float)mask[b * Sn + tid]) * -1e9f;

    float qr[64];
    {
        const float* qp = q + base + (size_t)tid * Hn;
#pragma unroll
        for (int d = 0; d < 64; d += 4) {
            float4 t4 = *(const float4*)(qp + d);
            qr[d] = t4.x; qr[d + 1] = t4.y; qr[d + 2] = t4.z; qr[d + 3] = t4.w;
        }
    }
    __syncthreads();

    float mx = -1e30f;
    float* scr = sc + tid * 129;
    for (int j = 0; j < 128; j++) {
        float dot = 0.f;
#pragma unroll
        for (int d = 0; d < 64; d++) dot += qr[d] * ks[j * 64 + d];
        float s = dot * scale + ms[j];
        scr[j] = s;
        mx = fmaxf(mx, s);
    }
    float sum = 0.f;
    for (int j = 0; j < 128; j++) {
        float e = __expf(scr[j] - mx);
        scr[j] = e; sum += e;
    }
    float inv = 1.0f / sum;
    float acc[64];
#pragma unroll
    for (int d = 0; d < 64; d++) acc[d] = 0.f;
    for (int j = 0; j < 128; j++) {
        float p = scr[j] * inv;
#pragma unroll
        for (int d = 0; d < 64; d++) acc[d] += p * vs[j * 64 + d];
    }
    float* op = ctx + base + (size_t)tid * Hn;
#pragma unroll
    for (int d = 0; d < 64; d += 4) {
        *(float4*)(op + d) = make_float4(acc[d], acc[d + 1], acc[d + 2], acc[d + 3]);
    }
}

// ---------------- decoder init ----------------
__global__ void __launch_bounds__(256) init_dec_kernel(
    const float* __restrict__ ew, const float* __restrict__ ep,
    const float* __restrict__ et, const float* __restrict__ g,
    const float* __restrict__ bb, float* __restrict__ xt)
{
    float vals[3]; float sum = 0.f, sq = 0.f;
#pragma unroll
    for (int i = 0; i < 3; i++) {
        int hh = threadIdx.x + i * 256;
        float v = ew[(size_t)101 * Hn + hh] + ep[hh] + et[hh];
        vals[i] = v; sum += v; sq += v * v;
    }
    float2 r = blockReduce2(sum, sq);
    float m = r.x * (1.f / Hn);
    float var = r.y * (1.f / Hn) - m * m;
    float rs = rsqrtf(var + 1e-12f);
#pragma unroll
    for (int i = 0; i < 3; i++) {
        int hh = threadIdx.x + i * 256;
        float o = (vals[i] - m) * rs * g[hh] + bb[hh];
        for (int bi = 0; bi < Bn; bi++) xt[bi * Hn + hh] = o;
    }
}

__global__ void init_hidden_kernel(const float* __restrict__ x, float* __restrict__ h) {
    int b = blockIdx.x;
    for (int hh = threadIdx.x; hh < Hn; hh += blockDim.x)
        h[b * Hn + hh] = x[((size_t)b * Sn + (Sn - 1)) * Hn + hh];
}

// ---------------- GRU GEMM: C[32, 2304] = X[32,768] @ W[2304,768]^T ----------------
__global__ void __launch_bounds__(256) gru_gemm_kernel(
    const float* __restrict__ X, const float* __restrict__ W, float* __restrict__ C)
{
    __shared__ float xs[32 * 128];
    int tid = threadIdx.x;
    int n = blockIdx.x * 64 + (tid & 63);
    int bg = (tid >> 6) * 8;
    float acc[8];
#pragma unroll
    for (int i = 0; i < 8; i++) acc[i] = 0.f;

    for (int k0 = 0; k0 < Hn; k0 += 128) {
        for (int idx = tid; idx < 32 * 128; idx += 256) {
            int bb = idx >> 7, kk = idx & 127;
            xs[idx] = X[bb * Hn + k0 + kk];
        }
        __syncthreads();
        const float* wp = W + (size_t)n * Hn + k0;
#pragma unroll
        for (int kk = 0; kk < 128; kk += 4) {
            float4 w4 = *(const float4*)(wp + kk);
#pragma unroll
            for (int i = 0; i < 8; i++) {
                const float* xr = &xs[(bg + i) * 128 + kk];
                acc[i] += xr[0] * w4.x + xr[1] * w4.y + xr[2] * w4.z + xr[3] * w4.w;
            }
        }
        __syncthreads();
    }
#pragma unroll
    for (int i = 0; i < 8; i++) C[(bg + i) * (3 * Hn) + n] = acc[i];
}

// ---------------- GRU gate ----------------
__global__ void __launch_bounds__(256) gru_gate_kernel(
    const float* __restrict__ gi, const float* __restrict__ gh,
    const float* __restrict__ b_ih, const float* __restrict__ b_hh,
    float* __restrict__ h, float* __restrict__ xt)
{
    int b = blockIdx.x;
    for (int hh = threadIdx.x; hh < Hn; hh += 256) {
        float ir = gi[b * 3 * Hn + hh]          + b_ih[hh];
        float iz = gi[b * 3 * Hn + Hn + hh]     + b_ih[Hn + hh];
        float in_ = gi[b * 3 * Hn + 2 * Hn + hh] + b_ih[2 * Hn + hh];
        float hr = gh[b * 3 * Hn + hh]          + b_hh[hh];
        float hz = gh[b * 3 * Hn + Hn + hh]     + b_hh[Hn + hh];
        float hn = gh[b * 3 * Hn + 2 * Hn + hh] + b_hh[2 * Hn + hh];
        float r = 1.f / (1.f + __expf(-(ir + hr)));
        float z = 1.f / (1.f + __expf(-(iz + hz)));
        float n = tanhf(in_ + r * hn);
        float hold = h[b * Hn + hh];
        float hnew = (1.f - z) * n + z * hold;
        h[b * Hn + hh] = hnew;
        xt[b * Hn + hh] = hnew;
    }
}

// ---------------- logits ----------------
__global__ void gru_logits_kernel(
    const float* __restrict__ h, const float* __restrict__ Wf,
    const float* __restrict__ bf, float* __restrict__ out, int t)
{
    int b = blockIdx.x, c = blockIdx.y;
    int lane = threadIdx.x;
    float acc = 0.f;
    for (int k = lane; k < Hn; k += 32) acc += h[b * Hn + k] * Wf[k * Cn + c];
#pragma unroll
    for (int o = 16; o > 0; o >>= 1) acc += __shfl_xor_sync(0xffffffffu, acc, o);
    if (lane == 0) out[(b * Tn + t) * Cn + c] = acc + bf[c];
}

// ---------------- host launcher ----------------
extern "C" void kernel_launch(void* const* d_in, const int* in_sizes, int n_in,
                              void* d_out, int out_size)
{
    const int*   ids      = (const int*)  d_in[0];
    const int*   am       = (const int*)  d_in[1];
    const float* emb_word = (const float*)d_in[2];
    const float* emb_pos  = (const float*)d_in[3];
    const float* emb_tok  = (const float*)d_in[4];
    const float* ln_emb_g = (const float*)d_in[5];
    const float* ln_emb_b = (const float*)d_in[6];
    const float* Wq = (const float*)d_in[7];
    const float* Wk = (const float*)d_in[8];
    const float* Wv = (const float*)d_in[9];
    const float* Wo = (const float*)d_in[10];
    const float* bq = (const float*)d_in[11];
    const float* bk = (const float*)d_in[12];
    const float* bv = (const float*)d_in[13];
    const float* bo = (const float*)d_in[14];
    const float* ln1g = (const float*)d_in[15];
    const float* ln1b = (const float*)d_in[16];
    const float* W1 = (const float*)d_in[17];
    const float* b1 = (const float*)d_in[18];
    const float* W2 = (const float*)d_in[19];
    const float* b2 = (const float*)d_in[20];
    const float* ln2g = (const float*)d_in[21];
    const float* ln2b = (const float*)d_in[22];
    const float* W_ih = (const float*)d_in[23];
    const float* W_hh = (const float*)d_in[24];
    const float* b_ih = (const float*)d_in[25];
    const float* b_hh = (const float*)d_in[26];
    const float* Wf = (const float*)d_in[27];
    const float* bf = (const float*)d_in[28];
    float* out = (float*)d_out;

    float *x, *q, *k, *v, *ctx, *y, *ff, *xt, *h, *gi, *gh;
    cudaGetSymbolAddress((void**)&x,   g_x);
    cudaGetSymbolAddress((void**)&q,   g_q);
    cudaGetSymbolAddress((void**)&k,   g_k);
    cudaGetSymbolAddress((void**)&v,   g_v);
    cudaGetSymbolAddress((void**)&ctx, g_ctx);
    cudaGetSymbolAddress((void**)&y,   g_y);
    cudaGetSymbolAddress((void**)&ff,  g_ff);
    cudaGetSymbolAddress((void**)&xt,  g_xt);
    cudaGetSymbolAddress((void**)&h,   g_h);
    cudaGetSymbolAddress((void**)&gi,  g_gi);
    cudaGetSymbolAddress((void**)&gh,  g_gh);

    cudaFuncSetAttribute(attn_kernel, cudaFuncAttributeMaxDynamicSharedMemorySize, ATTN_SMEM);

    embed_ln_kernel<<<Mrows, 256>>>(ids, emb_word, emb_pos, emb_tok, ln_emb_g, ln_emb_b, x);

    dim3 gQKV(Hn / 64, Mrows / 128, 3);  // (12, 32, 3)
    dim3 gHH(Hn / 64, Mrows / 128);      // (12, 32)
    dim3 gHF(FFn / 64, Mrows / 128);     // (48, 32)

    for (int l = 0; l < Ln; l++) {
        const float* wq = Wq + (size_t)l * Hn * Hn;
        const float* wk = Wk + (size_t)l * Hn * Hn;
        const float* wv = Wv + (size_t)l * Hn * Hn;
        const float* wo = Wo + (size_t)l * Hn * Hn;
        qkv_gemm_kernel<<<gQKV, 256>>>(x, wq, wk, wv, bq + l * Hn, bk + l * Hn, bv + l * Hn, q, k, v);
        attn_kernel<<<dim3(NHn, Bn), 128, ATTN_SMEM>>>(q, k, v, am, ctx);
        tgemm_kernel<<<gHH, 256>>>(ctx, wo, bo + l * Hn, y, Hn, Hn, 0);
        add_ln_kernel<<<Mrows, 256>>>(x, y, ln1g + l * Hn, ln1b + l * Hn);
        tgemm_kernel<<<gHF, 256>>>(x, W1 + (size_t)l * Hn * FFn, b1 + l * FFn, ff, FFn, Hn, 1);
        tgemm_kernel<<<gHH, 256>>>(ff, W2 + (size_t)l * FFn * Hn, b2 + l * Hn, y, Hn, FFn, 0);
        add_ln_kernel<<<Mrows, 256>>>(x, y, ln2g + l * Hn, ln2b + l * Hn);
    }

    init_dec_kernel<<<1, 256>>>(emb_word, emb_pos, emb_tok, ln_emb_g, ln_emb_b, xt);
    init_hidden_kernel<<<Bn, 256>>>(x, h);

    for (int t = 0; t < Tn; t++) {
        gru_gemm_kernel<<<3 * Hn / 64, 256>>>(xt, W_ih, gi);
        gru_gemm_kernel<<<3 * Hn / 64, 256>>>(h, W_hh, gh);
        gru_gate_kernel<<<Bn, 256>>>(gi, gh, b_ih, b_hh, h, xt);
        gru_logits_kernel<<<dim3(Bn, Cn), 32>>>(h, Wf, bf, out, t);
    }
}

// round 13
// speedup vs baseline: 1.4306x; 1.4306x over previous
#include <cuda_runtime.h>
#include <math.h>
#include <stdint.h>

#define Bn 32
#define Sn 128
#define Hn 768
#define NHn 12
#define DHn 64
#define FFn 3072
#define Ln 12
#define Tn 10
#define Cn 16
#define Mrows (Bn*Sn)

// ---------------- scratch (static device allocations; no cudaMalloc) ----------------
__device__ float g_x  [Mrows*Hn];
__device__ float g_xr [Mrows*Hn];   // tf32-rounded copy of x (GEMM A input)
__device__ float g_q  [Mrows*Hn];
__device__ float g_k  [Mrows*Hn];
__device__ float g_v  [Mrows*Hn];
__device__ float g_ctx[Mrows*Hn];
__device__ float g_y  [Mrows*Hn];
__device__ float g_ff [Mrows*FFn];
__device__ float g_xt [Bn*Hn];
__device__ float g_h  [Bn*Hn];
__device__ float g_gi [Bn*3*Hn];
__device__ float g_gh [Bn*3*Hn];
// transposed + tf32-rounded weights, [N][K] layout per layer
__device__ float g_wq [Ln*Hn*Hn];
__device__ float g_wk [Ln*Hn*Hn];
__device__ float g_wv [Ln*Hn*Hn];
__device__ float g_wo [Ln*Hn*Hn];
__device__ float g_w1 [Ln*Hn*FFn];
__device__ float g_w2 [Ln*FFn*Hn];

// ---------------- helpers ----------------
__device__ __forceinline__ float2 blockReduce2(float a, float b) {
    __shared__ float ra[8], rb[8];
    int lane = threadIdx.x & 31, w = threadIdx.x >> 5;
#pragma unroll
    for (int o = 16; o > 0; o >>= 1) {
        a += __shfl_xor_sync(0xffffffffu, a, o);
        b += __shfl_xor_sync(0xffffffffu, b, o);
    }
    if (lane == 0) { ra[w] = a; rb[w] = b; }
    __syncthreads();
    if (threadIdx.x == 0) {
        float sa = 0.f, sb = 0.f;
#pragma unroll
        for (int i = 0; i < 8; i++) { sa += ra[i]; sb += rb[i]; }
        ra[0] = sa; rb[0] = sb;
    }
    __syncthreads();
    return make_float2(ra[0], rb[0]);
}

__device__ __forceinline__ float rnd_tf32(float f) {
    uint32_t r;
    asm("cvt.rna.tf32.f32 %0, %1;" : "=r"(r) : "f"(f));
    return __uint_as_float(r);
}

__device__ __forceinline__ void cp16(uint32_t dst, const void* src) {
    asm volatile("cp.async.cg.shared.global [%0], [%1], 16;" :: "r"(dst), "l"(src));
}

__device__ __forceinline__ uint32_t smem_u32(const void* p) {
    uint32_t a;
    asm("{ .reg .u64 t; cvta.to.shared.u64 t, %1; cvt.u32.u64 %0, t; }" : "=r"(a) : "l"(p));
    return a;
}

__device__ __forceinline__ void ldm_x4(uint32_t* r, uint32_t addr) {
    asm volatile("ldmatrix.sync.aligned.m8n8.x4.shared.b16 {%0,%1,%2,%3}, [%4];"
        : "=r"(r[0]), "=r"(r[1]), "=r"(r[2]), "=r"(r[3]) : "r"(addr));
}

__device__ __forceinline__ void mma_tf32(float* c, const uint32_t* a, const uint32_t* b) {
    asm volatile(
        "mma.sync.aligned.m16n8k8.row.col.f32.tf32.tf32.f32 "
        "{%0,%1,%2,%3}, {%4,%5,%6,%7}, {%8,%9}, {%0,%1,%2,%3};"
        : "+f"(c[0]), "+f"(c[1]), "+f"(c[2]), "+f"(c[3])
        : "r"(a[0]), "r"(a[1]), "r"(a[2]), "r"(a[3]), "r"(b[0]), "r"(b[1]));
}

// ---------------- TF32 GEMM, ldmatrix operand path ----------------
// C[M,Ntot] = A[M,K] @ Bt[Ntot,K]^T + bias (opt exact GELU, rounded out).
// Tile 128x64, K chunks of 32 per stage, 4 stages, 256 threads (8 warps 4Mx2N),
// warp tile 32x32. A,Bt pre-rounded to tf32. 128B swizzled rows.
#define A_STG 16384
#define B_STG 8192
#define STG (A_STG + B_STG)
#define NSTG4 4
#define GEMM_SMEM (NSTG4 * STG)

__device__ __forceinline__ void tgemm_core(
    const float* __restrict__ A, const float* __restrict__ Bt,
    const float* __restrict__ bias, float* __restrict__ C,
    int Ntot, int K, int act, int m0, int n0, char* sm)
{
    int tid = threadIdx.x;
    int warp = tid >> 5, lane = tid & 31;
    int wm = (warp >> 1) * 32;   // 4 warp rows
    int wn = (warp & 1) * 32;    // 2 warp cols
    int g = lane >> 2, t = lane & 3;       // mma fragment coords
    int mi = lane >> 3, mr = lane & 7;     // ldmatrix coords

    uint32_t smu = smem_u32(sm);

    // per-lane ldmatrix row bases (byte offsets within a stage) and group offsets
    uint32_t a_rb0 = (uint32_t)((wm + (mi & 1) * 8 + mr) * 128);
    uint32_t a_rb1 = a_rb0 + 16 * 128;
    uint32_t b_rb0 = (uint32_t)(A_STG + (wn + (mi >> 1) * 8 + mr) * 128);
    uint32_t b_rb1 = b_rb0 + 16 * 128;
    uint32_t agoff[4], bgoff[4];
#pragma unroll
    for (int ks = 0; ks < 4; ks++) {
        agoff[ks] = (uint32_t)((((ks * 2 + (mi >> 1)) ^ mr) << 4));
        bgoff[ks] = (uint32_t)((((ks * 2 + (mi & 1)) ^ mr) << 4));
    }

    float acc[2][4][4];
#pragma unroll
    for (int s = 0; s < 2; s++)
#pragma unroll
        for (int nt = 0; nt < 4; nt++)
#pragma unroll
            for (int r = 0; r < 4; r++) acc[s][nt][r] = 0.f;

    int NC = K >> 5;

    auto load_chunk = [&](int c) {
        uint32_t sb = smu + (uint32_t)(c & 3) * STG;
        const float* Ac = A + (size_t)m0 * K + c * 32;
#pragma unroll
        for (int i = 0; i < 4; i++) {
            int idx = tid + i * 256;            // 0..1023
            int row = idx >> 3, c16 = idx & 7;
            uint32_t off = (uint32_t)(row * 128 + ((c16 ^ (row & 7)) << 4));
            cp16(sb + off, Ac + (size_t)row * K + c16 * 4);
        }
        const float* Bc = Bt + (size_t)n0 * K + c * 32;
#pragma unroll
        for (int i = 0; i < 2; i++) {
            int idx = tid + i * 256;            // 0..511
            int row = idx >> 3, c16 = idx & 7;
            uint32_t off = (uint32_t)(row * 128 + ((c16 ^ (row & 7)) << 4));
            cp16(sb + A_STG + off, Bc + (size_t)row * K + c16 * 4);
        }
        asm volatile("cp.async.commit_group;");
    };

    load_chunk(0); load_chunk(1); load_chunk(2);

    for (int c = 0; c < NC; ++c) {
        if (c + 1 < NC) asm volatile("cp.async.wait_group 2;");
        else            asm volatile("cp.async.wait_group 0;");
        __syncthreads();

        uint32_t sb = smu + (uint32_t)(c & 3) * STG;
        uint32_t ar0 = sb + a_rb0, ar1 = sb + a_rb1;
        uint32_t br0 = sb + b_rb0, br1 = sb + b_rb1;

#pragma unroll
        for (int ks = 0; ks < 4; ++ks) {
            uint32_t af[2][4], bf[2][4];
            ldm_x4(af[0], ar0 + agoff[ks]);
            ldm_x4(af[1], ar1 + agoff[ks]);
            ldm_x4(bf[0], br0 + bgoff[ks]);
            ldm_x4(bf[1], br1 + bgoff[ks]);
#pragma unroll
            for (int s = 0; s < 2; s++) {
                mma_tf32(acc[s][0], af[s], &bf[0][0]);
                mma_tf32(acc[s][1], af[s], &bf[0][2]);
                mma_tf32(acc[s][2], af[s], &bf[1][0]);
                mma_tf32(acc[s][3], af[s], &bf[1][2]);
            }
        }

        if (c + 3 < NC) load_chunk(c + 3);
    }

    // epilogue
#pragma unroll
    for (int s = 0; s < 2; s++) {
        int r0 = m0 + wm + s * 16 + g;
#pragma unroll
        for (int nt = 0; nt < 4; nt++) {
            int cc = n0 + wn + nt * 8 + t * 2;
            float b0 = bias[cc], b1 = bias[cc + 1];
            float v0 = acc[s][nt][0] + b0, v1 = acc[s][nt][1] + b1;
            float v2 = acc[s][nt][2] + b0, v3 = acc[s][nt][3] + b1;
            if (act == 1) {
                v0 = rnd_tf32(0.5f * v0 * (1.0f + erff(v0 * 0.70710678118654752f)));
                v1 = rnd_tf32(0.5f * v1 * (1.0f + erff(v1 * 0.70710678118654752f)));
                v2 = rnd_tf32(0.5f * v2 * (1.0f + erff(v2 * 0.70710678118654752f)));
                v3 = rnd_tf32(0.5f * v3 * (1.0f + erff(v3 * 0.70710678118654752f)));
            }
            *(float2*)&C[(size_t)r0 * Ntot + cc] = make_float2(v0, v1);
            *(float2*)&C[(size_t)(r0 + 8) * Ntot + cc] = make_float2(v2, v3);
        }
    }
}

__global__ void __launch_bounds__(256, 2) tgemm_kernel(
    const float* __restrict__ A, const float* __restrict__ Bt,
    const float* __restrict__ bias, float* __restrict__ C,
    int Ntot, int K, int act)
{
    extern __shared__ char dsm[];
    tgemm_core(A, Bt, bias, C, Ntot, K, act, blockIdx.y * 128, blockIdx.x * 64, dsm);
}

__global__ void __launch_bounds__(256, 2) qkv_gemm_kernel(
    const float* __restrict__ A,
    const float* __restrict__ Wq, const float* __restrict__ Wk, const float* __restrict__ Wv,
    const float* __restrict__ bq, const float* __restrict__ bk, const float* __restrict__ bv,
    float* __restrict__ q, float* __restrict__ k, float* __restrict__ v)
{
    extern __shared__ char dsm[];
    int z = blockIdx.z;
    const float* B = (z == 0) ? Wq : (z == 1) ? Wk : Wv;
    const float* bias = (z == 0) ? bq : (z == 1) ? bk : bv;
    float* C = (z == 0) ? q : (z == 1) ? k : v;
    tgemm_core(A, B, bias, C, Hn, Hn, 0, blockIdx.y * 128, blockIdx.x * 64, dsm);
}

// ---------------- weight transpose + rna: in[K][N] -> out[N][K], per layer (z) ----------------
__global__ void __launch_bounds__(256) transpose_rna_kernel(
    const float* __restrict__ in, float* __restrict__ out, int K, int N)
{
    __shared__ float ts[32][33];
    int l = blockIdx.z;
    const float* ip = in + (size_t)l * K * N;
    float* op = out + (size_t)l * K * N;
    int k0 = blockIdx.y * 32, n0 = blockIdx.x * 32;
    int tx = threadIdx.x & 31, ty = threadIdx.x >> 5;   // 32x8
#pragma unroll
    for (int r = 0; r < 4; r++)
        ts[ty + r * 8][tx] = ip[(size_t)(k0 + ty + r * 8) * N + n0 + tx];
    __syncthreads();
#pragma unroll
    for (int r = 0; r < 4; r++)
        op[(size_t)(n0 + ty + r * 8) * K + k0 + tx] = rnd_tf32(ts[tx][ty + r * 8]);
}

// ---------------- embedding + LN (writes x fp32, xr tf32) ----------------
__global__ void __launch_bounds__(256) embed_ln_kernel(
    const int* __restrict__ ids, const float* __restrict__ ew,
    const float* __restrict__ ep, const float* __restrict__ et,
    const float* __restrict__ g, const float* __restrict__ bb,
    float* __restrict__ x, float* __restrict__ xr)
{
    int row = blockIdx.x;
    int s = row % Sn;
    int id = ids[row];
    float vals[3]; float sum = 0.f, sq = 0.f;
#pragma unroll
    for (int i = 0; i < 3; i++) {
        int hh = threadIdx.x + i * 256;
        float v = ew[(size_t)id * Hn + hh] + ep[(size_t)s * Hn + hh] + et[hh];
        vals[i] = v; sum += v; sq += v * v;
    }
    float2 r = blockReduce2(sum, sq);
    float m = r.x * (1.f / Hn);
    float var = r.y * (1.f / Hn) - m * m;
    float rs = rsqrtf(var + 1e-12f);
#pragma unroll
    for (int i = 0; i < 3; i++) {
        int hh = threadIdx.x + i * 256;
        float o = (vals[i] - m) * rs * g[hh] + bb[hh];
        x [(size_t)row * Hn + hh] = o;
        xr[(size_t)row * Hn + hh] = rnd_tf32(o);
    }
}

// ---------------- residual add + LN: x = LN(x + t); xr = tf32(x) ----------------
__global__ void __launch_bounds__(256) add_ln_kernel(
    float* __restrict__ x, const float* __restrict__ t,
    const float* __restrict__ g, const float* __restrict__ bb,
    float* __restrict__ xr)
{
    size_t base = (size_t)blockIdx.x * Hn;
    float vals[3]; float sum = 0.f, sq = 0.f;
#pragma unroll
    for (int i = 0; i < 3; i++) {
        int hh = threadIdx.x + i * 256;
        float v = x[base + hh] + t[base + hh];
        vals[i] = v; sum += v; sq += v * v;
    }
    float2 r = blockReduce2(sum, sq);
    float m = r.x * (1.f / Hn);
    float var = r.y * (1.f / Hn) - m * m;
    float rs = rsqrtf(var + 1e-12f);
#pragma unroll
    for (int i = 0; i < 3; i++) {
        int hh = threadIdx.x + i * 256;
        float o = (vals[i] - m) * rs * g[hh] + bb[hh];
        x [base + hh] = o;
        xr[base + hh] = rnd_tf32(o);
    }
}

// ---------------- fused attention per (head, batch); ctx written tf32-rounded ----------------
#define ATTN_SMEM ((128*64*2 + 128*129 + 128) * 4)
__global__ void __launch_bounds__(128) attn_kernel(
    const float* __restrict__ q, const float* __restrict__ k,
    const float* __restrict__ v, const int* __restrict__ mask,
    float* __restrict__ ctx)
{
    extern __shared__ float sm[];
    float* ks = sm;
    float* vs = sm + 128 * 64;
    float* sc = sm + 2 * 128 * 64;
    float* ms = sc + 128 * 129;
    int h = blockIdx.x, b = blockIdx.y;
    int tid = threadIdx.x;
    const float scale = 0.125f;
    size_t base = ((size_t)b * Sn) * Hn + h * DHn;

    for (int idx = tid; idx < 128 * 64; idx += 128) {
        int s = idx >> 6, d = idx & 63;
        ks[idx] = k[base + (size_t)s * Hn + d];
        vs[idx] = v[base + (size_t)s * Hn + d];
    }
    ms[tid] = (1.0f - (float)mask[b * Sn + tid]) * -1e9f;

    float qr[64];
    {
        const float* qp = q + base + (size_t)tid * Hn;
#pragma unroll
        for (int d = 0; d < 64; d += 4) {
            float4 t4 = *(const float4*)(qp + d);
            qr[d] = t4.x; qr[d + 1] = t4.y; qr[d + 2] = t4.z; qr[d + 3] = t4.w;
        }
    }
    __syncthreads();

    float mx = -1e30f;
    float* scr = sc + tid * 129;
    for (int j = 0; j < 128; j++) {
        float dot = 0.f;
#pragma unroll
        for (int d = 0; d < 64; d++) dot += qr[d] * ks[j * 64 + d];
        float s = dot * scale + ms[j];
        scr[j] = s;
        mx = fmaxf(mx, s);
    }
    float sum = 0.f;
    for (int j = 0; j < 128; j++) {
        float e = __expf(scr[j] - mx);
        scr[j] = e; sum += e;
    }
    float inv = 1.0f / sum;
    float acc[64];
#pragma unroll
    for (int d = 0; d < 64; d++) acc[d] = 0.f;
    for (int j = 0; j < 128; j++) {
        float p = scr[j] * inv;
#pragma unroll
        for (int d = 0; d < 64; d++) acc[d] += p * vs[j * 64 + d];
    }
    float* op = ctx + base + (size_t)tid * Hn;
#pragma unroll
    for (int d = 0; d < 64; d += 4) {
        *(float4*)(op + d) = make_float4(rnd_tf32(acc[d]), rnd_tf32(acc[d + 1]),
                                         rnd_tf32(acc[d + 2]), rnd_tf32(acc[d + 3]));
    }
}

// ---------------- decoder init ----------------
__global__ void __launch_bounds__(256) init_dec_kernel(
    const float* __restrict__ ew, const float* __restrict__ ep,
    const float* __restrict__ et, const float* __restrict__ g,
    const float* __restrict__ bb, float* __restrict__ xt)
{
    float vals[3]; float sum = 0.f, sq = 0.f;
#pragma unroll
    for (int i = 0; i < 3; i++) {
        int hh = threadIdx.x + i * 256;
        float v = ew[(size_t)101 * Hn + hh] + ep[hh] + et[hh];
        vals[i] = v; sum += v; sq += v * v;
    }
    float2 r = blockReduce2(sum, sq);
    float m = r.x * (1.f / Hn);
    float var = r.y * (1.f / Hn) - m * m;
    float rs = rsqrtf(var + 1e-12f);
#pragma unroll
    for (int i = 0; i < 3; i++) {
        int hh = threadIdx.x + i * 256;
        float o = (vals[i] - m) * rs * g[hh] + bb[hh];
        for (int bi = 0; bi < Bn; bi++) xt[bi * Hn + hh] = o;
    }
}

__global__ void init_hidden_kernel(const float* __restrict__ x, float* __restrict__ h) {
    int b = blockIdx.x;
    for (int hh = threadIdx.x; hh < Hn; hh += blockDim.x)
        h[b * Hn + hh] = x[((size_t)b * Sn + (Sn - 1)) * Hn + hh];
}

// ---------------- GRU GEMM: C[32, 2304] = X[32,768] @ W[2304,768]^T ----------------
__global__ void __launch_bounds__(256) gru_gemm_kernel(
    const float* __restrict__ X, const float* __restrict__ W, float* __restrict__ C)
{
    __shared__ float xs[32 * 128];
    int tid = threadIdx.x;
    int n = blockIdx.x * 64 + (tid & 63);
    int bg = (tid >> 6) * 8;
    float acc[8];
#pragma unroll
    for (int i = 0; i < 8; i++) acc[i] = 0.f;

    for (int k0 = 0; k0 < Hn; k0 += 128) {
        for (int idx = tid; idx < 32 * 128; idx += 256) {
            int bb = idx >> 7, kk = idx & 127;
            xs[idx] = X[bb * Hn + k0 + kk];
        }
        __syncthreads();
        const float* wp = W + (size_t)n * Hn + k0;
#pragma unroll
        for (int kk = 0; kk < 128; kk += 4) {
            float4 w4 = *(const float4*)(wp + kk);
#pragma unroll
            for (int i = 0; i < 8; i++) {
                const float* xr = &xs[(bg + i) * 128 + kk];
                acc[i] += xr[0] * w4.x + xr[1] * w4.y + xr[2] * w4.z + xr[3] * w4.w;
            }
        }
        __syncthreads();
    }
#pragma unroll
    for (int i = 0; i < 8; i++) C[(bg + i) * (3 * Hn) + n] = acc[i];
}

// ---------------- GRU gate ----------------
__global__ void __launch_bounds__(256) gru_gate_kernel(
    const float* __restrict__ gi, const float* __restrict__ gh,
    const float* __restrict__ b_ih, const float* __restrict__ b_hh,
    float* __restrict__ h, float* __restrict__ xt)
{
    int b = blockIdx.x;
    for (int hh = threadIdx.x; hh < Hn; hh += 256) {
        float ir = gi[b * 3 * Hn + hh]          + b_ih[hh];
        float iz = gi[b * 3 * Hn + Hn + hh]     + b_ih[Hn + hh];
        float in_ = gi[b * 3 * Hn + 2 * Hn + hh] + b_ih[2 * Hn + hh];
        float hr = gh[b * 3 * Hn + hh]          + b_hh[hh];
        float hz = gh[b * 3 * Hn + Hn + hh]     + b_hh[Hn + hh];
        float hn = gh[b * 3 * Hn + 2 * Hn + hh] + b_hh[2 * Hn + hh];
        float r = 1.f / (1.f + __expf(-(ir + hr)));
        float z = 1.f / (1.f + __expf(-(iz + hz)));
        float n = tanhf(in_ + r * hn);
        float hold = h[b * Hn + hh];
        float hnew = (1.f - z) * n + z * hold;
        h[b * Hn + hh] = hnew;
        xt[b * Hn + hh] = hnew;
    }
}

// ---------------- logits ----------------
__global__ void gru_logits_kernel(
    const float* __restrict__ h, const float* __restrict__ Wf,
    const float* __restrict__ bf, float* __restrict__ out, int t)
{
    int b = blockIdx.x, c = blockIdx.y;
    int lane = threadIdx.x;
    float acc = 0.f;
    for (int k = lane; k < Hn; k += 32) acc += h[b * Hn + k] * Wf[k * Cn + c];
#pragma unroll
    for (int o = 16; o > 0; o >>= 1) acc += __shfl_xor_sync(0xffffffffu, acc, o);
    if (lane == 0) out[(b * Tn + t) * Cn + c] = acc + bf[c];
}

// ---------------- host launcher ----------------
extern "C" void kernel_launch(void* const* d_in, const int* in_sizes, int n_in,
                              void* d_out, int out_size)
{
    const int*   ids      = (const int*)  d_in[0];
    const int*   am       = (const int*)  d_in[1];
    const float* emb_word = (const float*)d_in[2];
    const float* emb_pos  = (const float*)d_in[3];
    const float* emb_tok  = (const float*)d_in[4];
    const float* ln_emb_g = (const float*)d_in[5];
    const float* ln_emb_b = (const float*)d_in[6];
    const float* Wq = (const float*)d_in[7];
    const float* Wk = (const float*)d_in[8];
    const float* Wv = (const float*)d_in[9];
    const float* Wo = (const float*)d_in[10];
    const float* bq = (const float*)d_in[11];
    const float* bk = (const float*)d_in[12];
    const float* bv = (const float*)d_in[13];
    const float* bo = (const float*)d_in[14];
    const float* ln1g = (const float*)d_in[15];
    const float* ln1b = (const float*)d_in[16];
    const float* W1 = (const float*)d_in[17];
    const float* b1 = (const float*)d_in[18];
    const float* W2 = (const float*)d_in[19];
    const float* b2 = (const float*)d_in[20];
    const float* ln2g = (const float*)d_in[21];
    const float* ln2b = (const float*)d_in[22];
    const float* W_ih = (const float*)d_in[23];
    const float* W_hh = (const float*)d_in[24];
    const float* b_ih = (const float*)d_in[25];
    const float* b_hh = (const float*)d_in[26];
    const float* Wf = (const float*)d_in[27];
    const float* bf = (const float*)d_in[28];
    float* out = (float*)d_out;

    float *x, *xr, *q, *k, *v, *ctx, *y, *ff, *xt, *h, *gi, *gh;
    float *wq, *wk, *wv, *wo, *w1, *w2;
    cudaGetSymbolAddress((void**)&x,   g_x);
    cudaGetSymbolAddress((void**)&xr,  g_xr);
    cudaGetSymbolAddress((void**)&q,   g_q);
    cudaGetSymbolAddress((void**)&k,   g_k);
    cudaGetSymbolAddress((void**)&v,   g_v);
    cudaGetSymbolAddress((void**)&ctx, g_ctx);
    cudaGetSymbolAddress((void**)&y,   g_y);
    cudaGetSymbolAddress((void**)&ff,  g_ff);
    cudaGetSymbolAddress((void**)&xt,  g_xt);
    cudaGetSymbolAddress((void**)&h,   g_h);
    cudaGetSymbolAddress((void**)&gi,  g_gi);
    cudaGetSymbolAddress((void**)&gh,  g_gh);
    cudaGetSymbolAddress((void**)&wq,  g_wq);
    cudaGetSymbolAddress((void**)&wk,  g_wk);
    cudaGetSymbolAddress((void**)&wv,  g_wv);
    cudaGetSymbolAddress((void**)&wo,  g_wo);
    cudaGetSymbolAddress((void**)&w1,  g_w1);
    cudaGetSymbolAddress((void**)&w2,  g_w2);

    cudaFuncSetAttribute(attn_kernel, cudaFuncAttributeMaxDynamicSharedMemorySize, ATTN_SMEM);
    cudaFuncSetAttribute(tgemm_kernel, cudaFuncAttributeMaxDynamicSharedMemorySize, GEMM_SMEM);
    cudaFuncSetAttribute(qkv_gemm_kernel, cudaFuncAttributeMaxDynamicSharedMemorySize, GEMM_SMEM);

    // transpose + tf32-round weights: [K,N] -> [N,K]
    {
        dim3 b256(256);
        transpose_rna_kernel<<<dim3(Hn / 32, Hn / 32, Ln), b256>>>(Wq, wq, Hn, Hn);
        transpose_rna_kernel<<<dim3(Hn / 32, Hn / 32, Ln), b256>>>(Wk, wk, Hn, Hn);
        transpose_rna_kernel<<<dim3(Hn / 32, Hn / 32, Ln), b256>>>(Wv, wv, Hn, Hn);
        transpose_rna_kernel<<<dim3(Hn / 32, Hn / 32, Ln), b256>>>(Wo, wo, Hn, Hn);
        transpose_rna_kernel<<<dim3(FFn / 32, Hn / 32, Ln), b256>>>(W1, w1, Hn, FFn);
        transpose_rna_kernel<<<dim3(Hn / 32, FFn / 32, Ln), b256>>>(W2, w2, FFn, Hn);
    }

    embed_ln_kernel<<<Mrows, 256>>>(ids, emb_word, emb_pos, emb_tok, ln_emb_g, ln_emb_b, x, xr);

    dim3 gQKV(Hn / 64, Mrows / 128, 3);  // (12, 32, 3)
    dim3 gHH(Hn / 64, Mrows / 128);      // (12, 32)
    dim3 gHF(FFn / 64, Mrows / 128);     // (48, 32)

    for (int l = 0; l < Ln; l++) {
        qkv_gemm_kernel<<<gQKV, 256, GEMM_SMEM>>>(
            xr, wq + (size_t)l * Hn * Hn, wk + (size_t)l * Hn * Hn, wv + (size_t)l * Hn * Hn,
            bq + l * Hn, bk + l * Hn, bv + l * Hn, q, k, v);
        attn_kernel<<<dim3(NHn, Bn), 128, ATTN_SMEM>>>(q, k, v, am, ctx);
        tgemm_kernel<<<gHH, 256, GEMM_SMEM>>>(ctx, wo + (size_t)l * Hn * Hn, bo + l * Hn, y, Hn, Hn, 0);
        add_ln_kernel<<<Mrows, 256>>>(x, y, ln1g + l * Hn, ln1b + l * Hn, xr);
        tgemm_kernel<<<gHF, 256, GEMM_SMEM>>>(xr, w1 + (size_t)l * Hn * FFn, b1 + l * FFn, ff, FFn, Hn, 1);
        tgemm_kernel<<<gHH, 256, GEMM_SMEM>>>(ff, w2 + (size_t)l * FFn * Hn, b2 + l * Hn, y, Hn, FFn, 0);
        add_ln_kernel<<<Mrows, 256>>>(x, y, ln2g + l * Hn, ln2b + l * Hn, xr);
    }

    init_dec_kernel<<<1, 256>>>(emb_word, emb_pos, emb_tok, ln_emb_g, ln_emb_b, xt);
    init_hidden_kernel<<<Bn, 256>>>(x, h);

    for (int t = 0; t < Tn; t++) {
        gru_gemm_kernel<<<3 * Hn / 64, 256>>>(xt, W_ih, gi);
        gru_gemm_kernel<<<3 * Hn / 64, 256>>>(h, W_hh, gh);
        gru_gate_kernel<<<Bn, 256>>>(gi, gh, b_ih, b_hh, h, xt);
        gru_logits_kernel<<<dim3(Bn, Cn), 32>>>(h, Wf, bf, out, t);
    }
}